// round 14
// baseline (speedup 1.0000x reference)
#include <cuda_runtime.h>
#include <cstdint>

// ---------------------------------------------------------------------------
// DInPBlock: invo1 (32->64, s2) -> 5 dilated involutions -> concat -> bn+prelu
// Shapes: x (8,32,256,256) f32 ; out (8,320,128,128) f32
// o1 via conv-commute fusion; k_dil processes 2 rows per block.
// ---------------------------------------------------------------------------

#define NBATCH 8

__device__ float g_o1[(size_t)NBATCH * 64 * 128 * 128];   // 33.5 MB (L2-resident)

// dynamic-smem float offsets for k_o1
#define XR   0
#define PSM  24576
#define TSM  28672
#define KKO  32768
#define SSM  33920
#define W1T  38016
#define WRO  40064
#define WSP  41088
#define SC1  41376
#define SB1  41408
#define BSC  41440
#define BSB  41504
#define BPR  41568
#define K_O1_FLOATS 41632   // 166528 bytes

// ---------------------------------------------------------------------------
// k_o1: fused kgen1 + (xi*patches) + bn1 + prelu -> g_o1   (unchanged winner)
// ---------------------------------------------------------------------------
__global__ __launch_bounds__(512) void k_o1(const float* __restrict__ x,
                                            const float* __restrict__ w1_init,
                                            const float* __restrict__ w1_red,
                                            const float* __restrict__ s1_g,
                                            const float* __restrict__ s1_b,
                                            const float* __restrict__ s1_m,
                                            const float* __restrict__ s1_v,
                                            const float* __restrict__ w1_span,
                                            const float* __restrict__ bn1_g,
                                            const float* __restrict__ bn1_b,
                                            const float* __restrict__ bn1_m,
                                            const float* __restrict__ bn1_v,
                                            const float* __restrict__ pr1) {
    extern __shared__ float sh[];
    const int h = blockIdx.x;
    const int b = blockIdx.y;
    const int tid = threadIdx.x;
    const int p = tid & 127;
    const int quad = tid >> 7;

    for (int i = tid; i < 2048; i += 512) {
        int c = i >> 6, o = i & 63;
        sh[W1T + i] = w1_init[o * 32 + c];
    }
    for (int i = tid; i < 1024; i += 512) {
        int c = i >> 5, o = i & 31;
        sh[WRO + i] = w1_red[o * 32 + c];
    }
    if (tid < 288) sh[WSP + tid] = w1_span[tid];
    if (tid < 32) {
        int o = tid;
        float s = s1_g[o] * rsqrtf(s1_v[o] + 1e-5f);
        sh[SC1 + o] = s;
        sh[SB1 + o] = s1_b[o] - s1_m[o] * s;
    }
    if (tid >= 64 && tid < 128) {
        int c = tid - 64;
        float s = bn1_g[c] * rsqrtf(bn1_v[c] + 1e-3f);
        sh[BSC + c] = s;
        sh[BSB + c] = bn1_b[c] - bn1_m[c] * s;
        sh[BPR + c] = pr1[c];
    }

    const float* xb = x + (size_t)b * 32 * 65536;
#pragma unroll 1
    for (int i = tid; i < 6144; i += 512) {
        int rr = i / 2048;
        int rem = i - rr * 2048;
        int c = rem >> 6, v4 = rem & 63;
        int g = 2 * h - 1 + rr;
        float4 val = make_float4(0.f, 0.f, 0.f, 0.f);
        if (g >= 0)
            val = *(const float4*)(xb + ((size_t)c * 256 + g) * 256 + v4 * 4);
        *(float4*)(sh + XR + ((rr * 32 + c) << 8) + v4 * 4) = val;
    }
    __syncthreads();

#pragma unroll
    for (int l = 0; l < 8; l++) {
        int c = quad * 8 + l;
        const float* r1 = sh + XR + ((32 + c) << 8);
        const float* r2 = sh + XR + ((64 + c) << 8);
        sh[PSM + (c << 7) + p] = 0.25f * (r1[2 * p] + r1[2 * p + 1] + r2[2 * p] + r2[2 * p + 1]);
    }
    __syncthreads();

#pragma unroll
    for (int l = 0; l < 8; l++) {
        int o = quad * 8 + l;
        float acc = 0.f;
#pragma unroll
        for (int c = 0; c < 32; c++)
            acc = fmaf(sh[WRO + (c << 5) + o], sh[PSM + (c << 7) + p], acc);
        sh[TSM + (o << 7) + p] = fmaxf(fmaf(acc, sh[SC1 + o], sh[SB1 + o]), 0.f);
    }
    __syncthreads();

    if (quad < 3) {
#pragma unroll
        for (int jj = 0; jj < 3; jj++) {
            int j = quad * 3 + jj;
            float acc = 0.f;
#pragma unroll
            for (int o = 0; o < 32; o++)
                acc = fmaf(sh[WSP + j * 32 + o], sh[TSM + (o << 7) + p], acc);
            sh[KKO + (j << 7) + p] = acc;
        }
    }
    __syncthreads();

    {
        float kkr[9];
#pragma unroll
        for (int k = 0; k < 9; k++) kkr[k] = sh[KKO + (k << 7) + p];
#pragma unroll
        for (int l = 0; l < 8; l++) {
            int c = quad * 8 + l;
            float acc = 0.f;
#pragma unroll
            for (int ki = 0; ki < 3; ki++) {
                const float* xr = sh + XR + (((ki * 32) + c) << 8);
#pragma unroll
                for (int kj = 0; kj < 3; kj++) {
                    int col = 2 * p - 1 + kj;
                    float v = (col >= 0) ? xr[col] : 0.f;
                    acc = fmaf(kkr[ki * 3 + kj], v, acc);
                }
            }
            sh[SSM + (c << 7) + p] = acc;
        }
    }
    __syncthreads();

    float acc[16];
#pragma unroll
    for (int l = 0; l < 16; l++) acc[l] = 0.f;
#pragma unroll 4
    for (int c = 0; c < 32; c++) {
        float sv = sh[SSM + (c << 7) + p];
        const float4* wp = (const float4*)(sh + W1T + (c << 6) + (quad << 4));
#pragma unroll
        for (int w4 = 0; w4 < 4; w4++) {
            float4 wv = wp[w4];
            acc[4 * w4 + 0] = fmaf(sv, wv.x, acc[4 * w4 + 0]);
            acc[4 * w4 + 1] = fmaf(sv, wv.y, acc[4 * w4 + 1]);
            acc[4 * w4 + 2] = fmaf(sv, wv.z, acc[4 * w4 + 2]);
            acc[4 * w4 + 3] = fmaf(sv, wv.w, acc[4 * w4 + 3]);
        }
    }
    float* op = g_o1 + ((size_t)(b * 64 + (quad << 4)) << 14) + (h << 7) + p;
#pragma unroll
    for (int l = 0; l < 16; l++) {
        int c = (quad << 4) + l;
        float v = fmaf(acc[l], sh[BSC + c], sh[BSB + c]);
        op[(size_t)l << 14] = v > 0.f ? v : sh[BPR + c] * v;
    }
}

// ---------------------------------------------------------------------------
// k_dil: block = (branch, row-pair, batch). 512 threads =
// 4 out-quarters x 2 rows x 64 px-cols; each thread 2 px x 16 outputs.
// cs[2][64][128] (dynamic smem) holds both center rows; span serialized.
// ---------------------------------------------------------------------------
__global__ __launch_bounds__(512, 2) void k_dil(const float* __restrict__ wd_red,
                                                const float* __restrict__ sd_g,
                                                const float* __restrict__ sd_b,
                                                const float* __restrict__ sd_m,
                                                const float* __restrict__ sd_v,
                                                const float* __restrict__ wd_span,
                                                const float* __restrict__ bnd_g,
                                                const float* __restrict__ bnd_b,
                                                const float* __restrict__ bnd_m,
                                                const float* __restrict__ bnd_v,
                                                const float* __restrict__ prd,
                                                const float* __restrict__ bnf_g,
                                                const float* __restrict__ bnf_b,
                                                const float* __restrict__ bnf_m,
                                                const float* __restrict__ bnf_v,
                                                const float* __restrict__ prf,
                                                float* __restrict__ out) {
    extern __shared__ float cs[];     // [2][64][128] = 16384 floats (64 KB)
    __shared__ float wrT[64 * 64];    // 16 KB
    __shared__ float wsp[9 * 64];
    __shared__ float part[4 * 9 * 128];   // 18 KB (reused row 0 then row 1)
    __shared__ float ks[64], kb[64], os_[64], ob[64], opr[64], fs[64], fb[64], fpr[64];
    const int i = blockIdx.x;         // branch
    const int h0 = blockIdx.y << 1;   // first row of pair
    const int b = blockIdx.z;
    const int tid = threadIdx.x;
    const int p = tid & 63;
    const int r = (tid >> 6) & 1;
    const int q = tid >> 7;
    const int h = h0 + r;
    const float* base = g_o1 + ((size_t)b * 64 << 14);

    for (int t = tid; t < 16384; t += 512) {
        int row = t >> 13, c = (t >> 7) & 63, pc = t & 127;
        cs[t] = base[(c << 14) + ((h0 + row) << 7) + pc];
    }
    for (int t = tid; t < 4096; t += 512) {
        int o = t & 63, c = t >> 6;
        wrT[t] = wd_red[i * 4096 + o * 64 + c];
    }
    for (int t = tid; t < 576; t += 512) wsp[t] = wd_span[i * 576 + t];
    if (tid < 64) {
        int c = tid, g = i * 64 + c;
        float s1 = sd_g[g] * rsqrtf(sd_v[g] + 1e-5f);
        ks[c] = s1; kb[c] = sd_b[g] - sd_m[g] * s1;
        float s2 = bnd_g[g] * rsqrtf(bnd_v[g] + 1e-3f);
        os_[c] = s2; ob[c] = bnd_b[g] - bnd_m[g] * s2; opr[c] = prd[g];
        float s3 = bnf_g[g] * rsqrtf(bnf_v[g] + 1e-3f);
        fs[c] = s3; fb[c] = bnf_b[g] - bnf_m[g] * s3; fpr[c] = prf[g];
    }
    __syncthreads();

    // ---- 64x64 matvec for this thread's row: 2 px x 16 outputs ----
    const float* csr = cs + (r << 13);
    float acc0[16], acc1[16];
#pragma unroll
    for (int l = 0; l < 16; l++) { acc0[l] = 0.f; acc1[l] = 0.f; }
#pragma unroll 4
    for (int c = 0; c < 64; c++) {
        float xc0 = csr[(c << 7) + p];
        float xc1 = csr[(c << 7) + 64 + p];
        const float4* wp = (const float4*)(wrT + (c << 6) + (q << 4));
#pragma unroll
        for (int w4 = 0; w4 < 4; w4++) {
            float4 wv = wp[w4];
            acc0[4 * w4 + 0] = fmaf(xc0, wv.x, acc0[4 * w4 + 0]);
            acc0[4 * w4 + 1] = fmaf(xc0, wv.y, acc0[4 * w4 + 1]);
            acc0[4 * w4 + 2] = fmaf(xc0, wv.z, acc0[4 * w4 + 2]);
            acc0[4 * w4 + 3] = fmaf(xc0, wv.w, acc0[4 * w4 + 3]);
            acc1[4 * w4 + 0] = fmaf(xc1, wv.x, acc1[4 * w4 + 0]);
            acc1[4 * w4 + 1] = fmaf(xc1, wv.y, acc1[4 * w4 + 1]);
            acc1[4 * w4 + 2] = fmaf(xc1, wv.z, acc1[4 * w4 + 2]);
            acc1[4 * w4 + 3] = fmaf(xc1, wv.w, acc1[4 * w4 + 3]);
        }
    }
#pragma unroll
    for (int l = 0; l < 16; l++) {
        int o = (q << 4) + l;
        acc0[l] = fmaxf(fmaf(acc0[l], ks[o], kb[o]), 0.f);
        acc1[l] = fmaxf(fmaf(acc1[l], ks[o], kb[o]), 0.f);
    }

    // ---- span: serialized over rows (part reused) ----
    float kkv0[9], kkv1[9];
#pragma unroll 1
    for (int rr = 0; rr < 2; rr++) {
        if (r == rr) {
#pragma unroll
            for (int j = 0; j < 9; j++) {
                float s0 = 0.f, s1 = 0.f;
                const float* wj = wsp + j * 64 + (q << 4);
#pragma unroll
                for (int l = 0; l < 16; l++) {
                    s0 = fmaf(wj[l], acc0[l], s0);
                    s1 = fmaf(wj[l], acc1[l], s1);
                }
                part[((q * 9 + j) << 7) + p]      = s0;
                part[((q * 9 + j) << 7) + 64 + p] = s1;
            }
        }
        __syncthreads();
        if (r == rr) {
#pragma unroll
            for (int j = 0; j < 9; j++) {
                kkv0[j] = part[(j << 7) + p]      + part[((9 + j) << 7) + p] +
                          part[((18 + j) << 7) + p] + part[((27 + j) << 7) + p];
                kkv1[j] = part[(j << 7) + 64 + p] + part[((9 + j) << 7) + 64 + p] +
                          part[((18 + j) << 7) + 64 + p] + part[((27 + j) << 7) + 64 + p];
            }
        }
        __syncthreads();
    }

    // ---- dilated 3x3 apply + fused epilogue ----
    const int dil = 1 << i;
    int trow[3];
    int src[3];   // 0/1 = smem row, -1 = gmem, -2 = invalid
#pragma unroll
    for (int ki = 0; ki < 3; ki++) {
        int t = h + (ki - 1) * dil;
        trow[ki] = t;
        if ((unsigned)t >= 128u) src[ki] = -2;
        else {
            unsigned d = (unsigned)(t - h0);
            src[ki] = (d < 2u) ? (int)d : -1;
        }
    }
#pragma unroll 1
    for (int px = 0; px < 2; px++) {
        const int pp = p + (px << 6);
        float kkv[9];
#pragma unroll
        for (int j = 0; j < 9; j++) kkv[j] = px ? kkv1[j] : kkv0[j];
        int cc0 = pp - dil, cc2 = pp + dil;
        bool v0 = (unsigned)cc0 < 128u, v2 = (unsigned)cc2 < 128u;
        float* outp = out + ((size_t)(b * 320 + i * 64 + (q << 4)) << 14) + (h << 7) + pp;
#pragma unroll 2
        for (int cl = 0; cl < 16; cl++) {
            int c = (q << 4) + cl;
            float a = 0.f;
#pragma unroll
            for (int ki = 0; ki < 3; ki++) {
                if (src[ki] == -2) continue;
                if (src[ki] >= 0) {
                    const float* rp = cs + (src[ki] << 13) + (c << 7);
                    if (v0) a = fmaf(rp[cc0], kkv[ki * 3 + 0], a);
                    a = fmaf(rp[pp], kkv[ki * 3 + 1], a);
                    if (v2) a = fmaf(rp[cc2], kkv[ki * 3 + 2], a);
                } else {
                    const float* rp = base + (c << 14) + (trow[ki] << 7);
                    if (v0) a = fmaf(__ldg(rp + cc0), kkv[ki * 3 + 0], a);
                    a = fmaf(__ldg(rp + pp), kkv[ki * 3 + 1], a);
                    if (v2) a = fmaf(__ldg(rp + cc2), kkv[ki * 3 + 2], a);
                }
            }
            float z = fmaf(a, os_[c], ob[c]);
            z = z > 0.f ? z : opr[c] * z;
            float y = fmaf(z, fs[c], fb[c]);
            outp[(size_t)cl << 14] = y > 0.f ? y : fpr[c] * y;
        }
    }
}

// ---------------------------------------------------------------------------
extern "C" void kernel_launch(void* const* d_in, const int* in_sizes, int n_in,
                              void* d_out, int out_size) {
    const float* x       = (const float*)d_in[0];
    const float* w1_init = (const float*)d_in[1];
    const float* w1_red  = (const float*)d_in[2];
    const float* s1_g    = (const float*)d_in[3];
    const float* s1_b    = (const float*)d_in[4];
    const float* s1_m    = (const float*)d_in[5];
    const float* s1_v    = (const float*)d_in[6];
    const float* w1_span = (const float*)d_in[7];
    const float* bn1_g   = (const float*)d_in[8];
    const float* bn1_b   = (const float*)d_in[9];
    const float* bn1_m   = (const float*)d_in[10];
    const float* bn1_v   = (const float*)d_in[11];
    const float* pr1     = (const float*)d_in[12];
    const float* wd_red  = (const float*)d_in[13];
    const float* sd_g    = (const float*)d_in[14];
    const float* sd_b    = (const float*)d_in[15];
    const float* sd_m    = (const float*)d_in[16];
    const float* sd_v    = (const float*)d_in[17];
    const float* wd_span = (const float*)d_in[18];
    const float* bnd_g   = (const float*)d_in[19];
    const float* bnd_b   = (const float*)d_in[20];
    const float* bnd_m   = (const float*)d_in[21];
    const float* bnd_v   = (const float*)d_in[22];
    const float* prd     = (const float*)d_in[23];
    const float* bnf_g   = (const float*)d_in[24];
    const float* bnf_b   = (const float*)d_in[25];
    const float* bnf_m   = (const float*)d_in[26];
    const float* bnf_v   = (const float*)d_in[27];
    const float* prf     = (const float*)d_in[28];
    float* out = (float*)d_out;

    static int smem_set = 0;
    if (!smem_set) {
        cudaFuncSetAttribute(k_o1, cudaFuncAttributeMaxDynamicSharedMemorySize,
                             K_O1_FLOATS * 4);
        cudaFuncSetAttribute(k_dil, cudaFuncAttributeMaxDynamicSharedMemorySize,
                             16384 * 4);
        smem_set = 1;
    }

    k_o1<<<dim3(128, 8), 512, K_O1_FLOATS * 4>>>(
        x, w1_init, w1_red, s1_g, s1_b, s1_m, s1_v, w1_span,
        bn1_g, bn1_b, bn1_m, bn1_v, pr1);
    k_dil<<<dim3(5, 64, 8), 512, 16384 * 4>>>(
        wd_red, sd_g, sd_b, sd_m, sd_v, wd_span,
        bnd_g, bnd_b, bnd_m, bnd_v, prd,
        bnf_g, bnf_b, bnf_m, bnf_v, prf, out);
}

// round 16
// speedup vs baseline: 1.3186x; 1.3186x over previous
#include <cuda_runtime.h>
#include <cstdint>

// ---------------------------------------------------------------------------
// DInPBlock: invo1 (32->64, s2) -> 5 dilated involutions -> concat -> bn+prelu
// Shapes: x (8,32,256,256) f32 ; out (8,320,128,128) f32
// ---------------------------------------------------------------------------

#define NBATCH 8

__device__ float g_o1[(size_t)NBATCH * 64 * 128 * 128];   // 33.5 MB (L2-resident)

// dynamic-smem float offsets for k_o1
#define XR   0
#define PSM  24576
#define TSM  28672
#define KKO  32768
#define SSM  33920
#define W1T  38016
#define WRO  40064
#define WSP  41088
#define SC1  41376
#define SB1  41408
#define BSC  41440
#define BSB  41504
#define BPR  41568
#define K_O1_FLOATS 41632   // 166528 bytes

// ---------------------------------------------------------------------------
// k_o1: fused kgen1 + (xi*patches) + bn1 + prelu -> g_o1   (R13 winner)
// ---------------------------------------------------------------------------
__global__ __launch_bounds__(512) void k_o1(const float* __restrict__ x,
                                            const float* __restrict__ w1_init,
                                            const float* __restrict__ w1_red,
                                            const float* __restrict__ s1_g,
                                            const float* __restrict__ s1_b,
                                            const float* __restrict__ s1_m,
                                            const float* __restrict__ s1_v,
                                            const float* __restrict__ w1_span,
                                            const float* __restrict__ bn1_g,
                                            const float* __restrict__ bn1_b,
                                            const float* __restrict__ bn1_m,
                                            const float* __restrict__ bn1_v,
                                            const float* __restrict__ pr1) {
    extern __shared__ float sh[];
    const int h = blockIdx.x;
    const int b = blockIdx.y;
    const int tid = threadIdx.x;
    const int p = tid & 127;
    const int quad = tid >> 7;

    for (int i = tid; i < 2048; i += 512) {
        int c = i >> 6, o = i & 63;
        sh[W1T + i] = w1_init[o * 32 + c];
    }
    for (int i = tid; i < 1024; i += 512) {
        int c = i >> 5, o = i & 31;
        sh[WRO + i] = w1_red[o * 32 + c];
    }
    if (tid < 288) sh[WSP + tid] = w1_span[tid];
    if (tid < 32) {
        int o = tid;
        float s = s1_g[o] * rsqrtf(s1_v[o] + 1e-5f);
        sh[SC1 + o] = s;
        sh[SB1 + o] = s1_b[o] - s1_m[o] * s;
    }
    if (tid >= 64 && tid < 128) {
        int c = tid - 64;
        float s = bn1_g[c] * rsqrtf(bn1_v[c] + 1e-3f);
        sh[BSC + c] = s;
        sh[BSB + c] = bn1_b[c] - bn1_m[c] * s;
        sh[BPR + c] = pr1[c];
    }

    const float* xb = x + (size_t)b * 32 * 65536;
#pragma unroll 1
    for (int i = tid; i < 6144; i += 512) {
        int rr = i / 2048;
        int rem = i - rr * 2048;
        int c = rem >> 6, v4 = rem & 63;
        int g = 2 * h - 1 + rr;
        float4 val = make_float4(0.f, 0.f, 0.f, 0.f);
        if (g >= 0)
            val = *(const float4*)(xb + ((size_t)c * 256 + g) * 256 + v4 * 4);
        *(float4*)(sh + XR + ((rr * 32 + c) << 8) + v4 * 4) = val;
    }
    __syncthreads();

#pragma unroll
    for (int l = 0; l < 8; l++) {
        int c = quad * 8 + l;
        const float* r1 = sh + XR + ((32 + c) << 8);
        const float* r2 = sh + XR + ((64 + c) << 8);
        sh[PSM + (c << 7) + p] = 0.25f * (r1[2 * p] + r1[2 * p + 1] + r2[2 * p] + r2[2 * p + 1]);
    }
    __syncthreads();

#pragma unroll
    for (int l = 0; l < 8; l++) {
        int o = quad * 8 + l;
        float acc = 0.f;
#pragma unroll
        for (int c = 0; c < 32; c++)
            acc = fmaf(sh[WRO + (c << 5) + o], sh[PSM + (c << 7) + p], acc);
        sh[TSM + (o << 7) + p] = fmaxf(fmaf(acc, sh[SC1 + o], sh[SB1 + o]), 0.f);
    }
    __syncthreads();

    if (quad < 3) {
#pragma unroll
        for (int jj = 0; jj < 3; jj++) {
            int j = quad * 3 + jj;
            float acc = 0.f;
#pragma unroll
            for (int o = 0; o < 32; o++)
                acc = fmaf(sh[WSP + j * 32 + o], sh[TSM + (o << 7) + p], acc);
            sh[KKO + (j << 7) + p] = acc;
        }
    }
    __syncthreads();

    {
        float kkr[9];
#pragma unroll
        for (int k = 0; k < 9; k++) kkr[k] = sh[KKO + (k << 7) + p];
#pragma unroll
        for (int l = 0; l < 8; l++) {
            int c = quad * 8 + l;
            float acc = 0.f;
#pragma unroll
            for (int ki = 0; ki < 3; ki++) {
                const float* xr = sh + XR + (((ki * 32) + c) << 8);
#pragma unroll
                for (int kj = 0; kj < 3; kj++) {
                    int col = 2 * p - 1 + kj;
                    float v = (col >= 0) ? xr[col] : 0.f;
                    acc = fmaf(kkr[ki * 3 + kj], v, acc);
                }
            }
            sh[SSM + (c << 7) + p] = acc;
        }
    }
    __syncthreads();

    float acc[16];
#pragma unroll
    for (int l = 0; l < 16; l++) acc[l] = 0.f;
#pragma unroll 4
    for (int c = 0; c < 32; c++) {
        float sv = sh[SSM + (c << 7) + p];
        const float4* wp = (const float4*)(sh + W1T + (c << 6) + (quad << 4));
#pragma unroll
        for (int w4 = 0; w4 < 4; w4++) {
            float4 wv = wp[w4];
            acc[4 * w4 + 0] = fmaf(sv, wv.x, acc[4 * w4 + 0]);
            acc[4 * w4 + 1] = fmaf(sv, wv.y, acc[4 * w4 + 1]);
            acc[4 * w4 + 2] = fmaf(sv, wv.z, acc[4 * w4 + 2]);
            acc[4 * w4 + 3] = fmaf(sv, wv.w, acc[4 * w4 + 3]);
        }
    }
    float* op = g_o1 + ((size_t)(b * 64 + (quad << 4)) << 14) + (h << 7) + p;
#pragma unroll
    for (int l = 0; l < 16; l++) {
        int c = (quad << 4) + l;
        float v = fmaf(acc[l], sh[BSC + c], sh[BSB + c]);
        op[(size_t)l << 14] = v > 0.f ? v : sh[BPR + c] * v;
    }
}

// ---------------------------------------------------------------------------
// k_dil (R12 structure, tap-major apply): block = (branch,row,batch),
// 256 thr = 4 quarters x 64 px-cols; 2 px x 16 outputs per thread.
// ---------------------------------------------------------------------------
__global__ __launch_bounds__(256) void k_dil(const float* __restrict__ wd_red,
                                             const float* __restrict__ sd_g,
                                             const float* __restrict__ sd_b,
                                             const float* __restrict__ sd_m,
                                             const float* __restrict__ sd_v,
                                             const float* __restrict__ wd_span,
                                             const float* __restrict__ bnd_g,
                                             const float* __restrict__ bnd_b,
                                             const float* __restrict__ bnd_m,
                                             const float* __restrict__ bnd_v,
                                             const float* __restrict__ prd,
                                             const float* __restrict__ bnf_g,
                                             const float* __restrict__ bnf_b,
                                             const float* __restrict__ bnf_m,
                                             const float* __restrict__ bnf_v,
                                             const float* __restrict__ prf,
                                             float* __restrict__ out) {
    __shared__ float cs[64 * 128];
    __shared__ float wrT[64 * 64];
    __shared__ float wsp[9 * 64];
    __shared__ float part[4 * 9 * 128];
    __shared__ float ks[64], kb[64], os_[64], ob[64], opr[64], fs[64], fb[64], fpr[64];
    const int i = blockIdx.x;
    const int h = blockIdx.y;
    const int b = blockIdx.z;
    const int tid = threadIdx.x;
    const int q = tid >> 6;
    const int p = tid & 63;
    const float* base = g_o1 + ((size_t)b * 64 << 14);

    for (int t = tid; t < 8192; t += 256) {
        int c = t >> 7, pc = t & 127;
        cs[t] = base[(c << 14) + (h << 7) + pc];
    }
    for (int t = tid; t < 4096; t += 256) {
        int o = t & 63, c = t >> 6;
        wrT[t] = wd_red[i * 4096 + o * 64 + c];
    }
    for (int t = tid; t < 576; t += 256) wsp[t] = wd_span[i * 576 + t];
    if (tid < 64) {
        int c = tid, g = i * 64 + c;
        float s1 = sd_g[g] * rsqrtf(sd_v[g] + 1e-5f);
        ks[c] = s1; kb[c] = sd_b[g] - sd_m[g] * s1;
        float s2 = bnd_g[g] * rsqrtf(bnd_v[g] + 1e-3f);
        os_[c] = s2; ob[c] = bnd_b[g] - bnd_m[g] * s2; opr[c] = prd[g];
        float s3 = bnf_g[g] * rsqrtf(bnf_v[g] + 1e-3f);
        fs[c] = s3; fb[c] = bnf_b[g] - bnf_m[g] * s3; fpr[c] = prf[g];
    }
    __syncthreads();

    // ---- 64x64 matvec: 2 pixels x 16 outputs per thread ----
    float acc0[16], acc1[16];
#pragma unroll
    for (int l = 0; l < 16; l++) { acc0[l] = 0.f; acc1[l] = 0.f; }
#pragma unroll 4
    for (int c = 0; c < 64; c++) {
        float xc0 = cs[(c << 7) + p];
        float xc1 = cs[(c << 7) + 64 + p];
        const float4* wp = (const float4*)(wrT + (c << 6) + (q << 4));
#pragma unroll
        for (int w4 = 0; w4 < 4; w4++) {
            float4 wv = wp[w4];
            acc0[4 * w4 + 0] = fmaf(xc0, wv.x, acc0[4 * w4 + 0]);
            acc0[4 * w4 + 1] = fmaf(xc0, wv.y, acc0[4 * w4 + 1]);
            acc0[4 * w4 + 2] = fmaf(xc0, wv.z, acc0[4 * w4 + 2]);
            acc0[4 * w4 + 3] = fmaf(xc0, wv.w, acc0[4 * w4 + 3]);
            acc1[4 * w4 + 0] = fmaf(xc1, wv.x, acc1[4 * w4 + 0]);
            acc1[4 * w4 + 1] = fmaf(xc1, wv.y, acc1[4 * w4 + 1]);
            acc1[4 * w4 + 2] = fmaf(xc1, wv.z, acc1[4 * w4 + 2]);
            acc1[4 * w4 + 3] = fmaf(xc1, wv.w, acc1[4 * w4 + 3]);
        }
    }
#pragma unroll
    for (int l = 0; l < 16; l++) {
        int o = (q << 4) + l;
        acc0[l] = fmaxf(fmaf(acc0[l], ks[o], kb[o]), 0.f);
        acc1[l] = fmaxf(fmaf(acc1[l], ks[o], kb[o]), 0.f);
    }
#pragma unroll
    for (int j = 0; j < 9; j++) {
        float s0 = 0.f, s1 = 0.f;
        const float* wj = wsp + j * 64 + (q << 4);
#pragma unroll
        for (int l = 0; l < 16; l++) {
            s0 = fmaf(wj[l], acc0[l], s0);
            s1 = fmaf(wj[l], acc1[l], s1);
        }
        part[((q * 9 + j) << 7) + p]      = s0;
        part[((q * 9 + j) << 7) + 64 + p] = s1;
    }
    __syncthreads();

    // ---- dilated 3x3 apply: tap-major with immediate channel offsets ----
    const int dil = 1 << i;
#pragma unroll 1
    for (int px = 0; px < 2; px++) {
        const int pp = p + (px << 6);
        float kkv[9];
#pragma unroll
        for (int j = 0; j < 9; j++)
            kkv[j] = part[(j << 7) + pp] + part[((9 + j) << 7) + pp] +
                     part[((18 + j) << 7) + pp] + part[((27 + j) << 7) + pp];

        const int cc0 = pp - dil, cc2 = pp + dil;
        const bool v0 = (unsigned)cc0 < 128u, v2 = (unsigned)cc2 < 128u;
        const int rt = h - dil, rb = h + dil;
        const bool vt = rt >= 0, vb = rb < 128;

        float av[16];
#pragma unroll
        for (int l = 0; l < 16; l++) av[l] = 0.f;

        // middle row taps from smem (row h == cs)
        {
            const float* m0 = cs + (q << 4 << 7) + cc0;
            const float* m1 = cs + (q << 4 << 7) + pp;
            const float* m2 = cs + (q << 4 << 7) + cc2;
            float k3 = kkv[3], k4 = kkv[4], k5 = kkv[5];
            if (v0) {
#pragma unroll
                for (int l = 0; l < 16; l++) av[l] = fmaf(m0[l << 7], k3, av[l]);
            }
#pragma unroll
            for (int l = 0; l < 16; l++) av[l] = fmaf(m1[l << 7], k4, av[l]);
            if (v2) {
#pragma unroll
                for (int l = 0; l < 16; l++) av[l] = fmaf(m2[l << 7], k5, av[l]);
            }
        }
        // top/bottom rows from gmem: one pointer per tap, imm channel offsets
        const float* gq = base + ((size_t)(q << 4) << 14);
        if (vt) {
            const float* r0 = gq + (rt << 7);
            float k0 = kkv[0], k1 = kkv[1], k2 = kkv[2];
            if (v0) {
                const float* t0 = r0 + cc0;
#pragma unroll
                for (int l = 0; l < 16; l++) av[l] = fmaf(__ldg(t0 + ((size_t)l << 14)), k0, av[l]);
            }
            {
                const float* t1 = r0 + pp;
#pragma unroll
                for (int l = 0; l < 16; l++) av[l] = fmaf(__ldg(t1 + ((size_t)l << 14)), k1, av[l]);
            }
            if (v2) {
                const float* t2 = r0 + cc2;
#pragma unroll
                for (int l = 0; l < 16; l++) av[l] = fmaf(__ldg(t2 + ((size_t)l << 14)), k2, av[l]);
            }
        }
        if (vb) {
            const float* r2 = gq + (rb << 7);
            float k6 = kkv[6], k7 = kkv[7], k8 = kkv[8];
            if (v0) {
                const float* t0 = r2 + cc0;
#pragma unroll
                for (int l = 0; l < 16; l++) av[l] = fmaf(__ldg(t0 + ((size_t)l << 14)), k6, av[l]);
            }
            {
                const float* t1 = r2 + pp;
#pragma unroll
                for (int l = 0; l < 16; l++) av[l] = fmaf(__ldg(t1 + ((size_t)l << 14)), k7, av[l]);
            }
            if (v2) {
                const float* t2 = r2 + cc2;
#pragma unroll
                for (int l = 0; l < 16; l++) av[l] = fmaf(__ldg(t2 + ((size_t)l << 14)), k8, av[l]);
            }
        }
        // fused epilogue
        float* outp = out + ((size_t)(b * 320 + i * 64 + (q << 4)) << 14) + (h << 7) + pp;
#pragma unroll
        for (int l = 0; l < 16; l++) {
            int c = (q << 4) + l;
            float z = fmaf(av[l], os_[c], ob[c]);
            z = z > 0.f ? z : opr[c] * z;
            float y = fmaf(z, fs[c], fb[c]);
            outp[(size_t)l << 14] = y > 0.f ? y : fpr[c] * y;
        }
    }
}

// ---------------------------------------------------------------------------
extern "C" void kernel_launch(void* const* d_in, const int* in_sizes, int n_in,
                              void* d_out, int out_size) {
    const float* x       = (const float*)d_in[0];
    const float* w1_init = (const float*)d_in[1];
    const float* w1_red  = (const float*)d_in[2];
    const float* s1_g    = (const float*)d_in[3];
    const float* s1_b    = (const float*)d_in[4];
    const float* s1_m    = (const float*)d_in[5];
    const float* s1_v    = (const float*)d_in[6];
    const float* w1_span = (const float*)d_in[7];
    const float* bn1_g   = (const float*)d_in[8];
    const float* bn1_b   = (const float*)d_in[9];
    const float* bn1_m   = (const float*)d_in[10];
    const float* bn1_v   = (const float*)d_in[11];
    const float* pr1     = (const float*)d_in[12];
    const float* wd_red  = (const float*)d_in[13];
    const float* sd_g    = (const float*)d_in[14];
    const float* sd_b    = (const float*)d_in[15];
    const float* sd_m    = (const float*)d_in[16];
    const float* sd_v    = (const float*)d_in[17];
    const float* wd_span = (const float*)d_in[18];
    const float* bnd_g   = (const float*)d_in[19];
    const float* bnd_b   = (const float*)d_in[20];
    const float* bnd_m   = (const float*)d_in[21];
    const float* bnd_v   = (const float*)d_in[22];
    const float* prd     = (const float*)d_in[23];
    const float* bnf_g   = (const float*)d_in[24];
    const float* bnf_b   = (const float*)d_in[25];
    const float* bnf_m   = (const float*)d_in[26];
    const float* bnf_v   = (const float*)d_in[27];
    const float* prf     = (const float*)d_in[28];
    float* out = (float*)d_out;

    static int smem_set = 0;
    if (!smem_set) {
        cudaFuncSetAttribute(k_o1, cudaFuncAttributeMaxDynamicSharedMemorySize,
                             K_O1_FLOATS * 4);
        smem_set = 1;
    }

    k_o1<<<dim3(128, 8), 512, K_O1_FLOATS * 4>>>(
        x, w1_init, w1_red, s1_g, s1_b, s1_m, s1_v, w1_span,
        bn1_g, bn1_b, bn1_m, bn1_v, pr1);
    k_dil<<<dim3(5, 128, 8), 256>>>(wd_red, sd_g, sd_b, sd_m, sd_v, wd_span,
                                    bnd_g, bnd_b, bnd_m, bnd_v, prd,
                                    bnf_g, bnf_b, bnf_m, bnf_v, prf, out);
}